// round 14
// baseline (speedup 1.0000x reference)
#include <cuda_runtime.h>
#include <cuda_fp16.h>
#include <mma.h>
#include <cstdint>
#include <math.h>

using namespace nvcuda;

#define BATCH 32768
#define NLEN  1116
#define AROW  1120   // fp16 A row stride (padded)

#define HDIM  100

// ---------------------------------------------------------------------------
// fp16 copy of recon, written by wavelet, consumed by mlp GEMM (73.4 MB)
// ---------------------------------------------------------------------------
__device__ __half g_Ah[(size_t)BATCH * AROW];

// ---------------------------------------------------------------------------
// sym4 filters
// ---------------------------------------------------------------------------
__constant__ float c_LO[8] = {
    -0.010597401784997278f,  0.032883011666982945f,  0.030841381835986965f,
    -0.18703481171888114f,  -0.02798376941698385f,   0.6308807679295904f,
     0.7148465705525415f,    0.23037781330885523f};
__constant__ float c_HI[8] = {
    -0.23037781330885523f,   0.7148465705525415f,   -0.6308807679295904f,
    -0.02798376941698385f,   0.18703481171888114f,   0.030841381835986965f,
    -0.032883011666982945f, -0.010597401784997278f};

__device__ __forceinline__ float softt(float v, float t) {
    float av = fabsf(v);
    return (av > t) ? copysignf(av - t, v) : 0.0f;
}

// One DWT level, COMPILE-TIME size M, T threads. Fully unrolled inner loop.
template <int T, int M>
__device__ __forceinline__ void dwt_level(const float* cur, float* nxt, float* dd,
                                          int id, float t)
{
    constexpr int CH = ((M + T - 1) / T) | 1;   // odd -> <=2-way LDS conflicts
    const int j0 = id * CH;
    if (j0 < M) {
        const float* p = cur + 2 + 2 * j0;
        float w0 = p[0], w1 = p[1], w2 = p[2], w3 = p[3];
        float w4 = p[4], w5 = p[5], w6 = p[6], w7 = p[7];
#pragma unroll
        for (int jj = 0; jj < CH; ++jj) {
            const int j = j0 + jj;
            float lo = w0 * c_LO[7];
            lo = fmaf(w1, c_LO[6], lo); lo = fmaf(w2, c_LO[5], lo);
            lo = fmaf(w3, c_LO[4], lo); lo = fmaf(w4, c_LO[3], lo);
            lo = fmaf(w5, c_LO[2], lo); lo = fmaf(w6, c_LO[1], lo);
            lo = fmaf(w7, c_LO[0], lo);
            float hi = w0 * c_HI[7];
            hi = fmaf(w1, c_HI[6], hi); hi = fmaf(w2, c_HI[5], hi);
            hi = fmaf(w3, c_HI[4], hi); hi = fmaf(w4, c_HI[3], hi);
            hi = fmaf(w5, c_HI[2], hi); hi = fmaf(w6, c_HI[1], hi);
            hi = fmaf(w7, c_HI[0], hi);
            if (j < M) {
                nxt[8 + j] = lo;
                dd[j] = softt(hi, t);
            }
            if (jj + 1 < CH) {
                w0 = w2; w1 = w3; w2 = w4; w3 = w5; w4 = w6; w5 = w7;
                float2 nx = *(const float2*)(p + 8 + 2 * jj);   // immediate offset
                w6 = nx.x; w7 = nx.y;                            // lookahead slack ok
            }
        }
    }
    if (id < 6) nxt[2 + id] = 0.0f;
    if (id < 8) nxt[8 + M + id] = 0.0f;
}

// One IDWT level, COMPILE-TIME pair count P (smem -> smem).
template <int T, int P>
__device__ __forceinline__ void idwt_level(const float* abase, const float* dd,
                                           float* obase, int id)
{
    constexpr int CH = ((P + T - 1) / T) | 1;
    const int p0 = id * CH;
    if (p0 < P) {
        float a0 = abase[p0], a1 = abase[p0 + 1], a2 = abase[p0 + 2], a3 = abase[p0 + 3];
        float d0 = dd[p0],    d1 = dd[p0 + 1],    d2 = dd[p0 + 2],    d3 = dd[p0 + 3];
#pragma unroll
        for (int jj = 0; jj < CH; ++jj) {
            const int p = p0 + jj;
            float ye = a0 * c_LO[1];
            ye = fmaf(a1, c_LO[3], ye); ye = fmaf(a2, c_LO[5], ye); ye = fmaf(a3, c_LO[7], ye);
            ye = fmaf(d0, c_HI[1], ye); ye = fmaf(d1, c_HI[3], ye);
            ye = fmaf(d2, c_HI[5], ye); ye = fmaf(d3, c_HI[7], ye);
            float yo = a0 * c_LO[0];
            yo = fmaf(a1, c_LO[2], yo); yo = fmaf(a2, c_LO[4], yo); yo = fmaf(a3, c_LO[6], yo);
            yo = fmaf(d0, c_HI[0], yo); yo = fmaf(d1, c_HI[2], yo);
            yo = fmaf(d2, c_HI[4], yo); yo = fmaf(d3, c_HI[6], yo);
            if (p < P) ((float2*)obase)[p] = make_float2(ye, yo);
            if (jj + 1 < CH) {
                a0 = a1; a1 = a2; a2 = a3; a3 = abase[p0 + jj + 4];   // lookahead ok
                d0 = d1; d1 = d2; d2 = d3; d3 = dd[p0 + jj + 4];
            }
        }
    }
}

// ---------------------------------------------------------------------------
// Kernel 1: per-row 7-level DWT -> soft threshold -> IDWT.
// Final synthesis level writes DIRECTLY to gmem (fp32 recon + fp16 g_Ah),
// skipping the smem staging + copy-out of earlier rounds.
// ---------------------------------------------------------------------------
__global__ __launch_bounds__(128) void wavelet_kernel(
    const float* __restrict__ x,
    const float* __restrict__ thr,
    float* __restrict__ recon)
{
    __shared__ __align__(16) float bufA[1140];
    __shared__ __align__(16) float bufB[1140];
    __shared__ __align__(16) float dbuf[1152];

    const int tid = threadIdx.x;
    const int row = blockIdx.x;
    const float t = fmaxf(thr[0], 0.01f);

    {
        const float4* xr = (const float4*)(x + (size_t)row * NLEN);
        float4* dst = (float4*)(bufA + 8);
        for (int i = tid; i < 279; i += 128) dst[i] = xr[i];
        if (tid < 6) bufA[2 + tid] = 0.0f;
        if (tid < 8) bufA[8 + NLEN + tid] = 0.0f;
    }
    __syncthreads();

    dwt_level<128, 561>(bufA, bufB, dbuf + 0,   tid, t);
    __syncthreads();
    dwt_level<128, 284>(bufB, bufA, dbuf + 561, tid, t);
    __syncthreads();
    dwt_level<128, 145>(bufA, bufB, dbuf + 845, tid, t);
    __syncthreads();

    if (tid < 32) {
        const int lane = tid;
        dwt_level<32, 76>(bufB, bufA, dbuf + 990,  lane, t);
        __syncwarp();
        dwt_level<32, 41>(bufA, bufB, dbuf + 1066, lane, t);
        __syncwarp();
        dwt_level<32, 24>(bufB, bufA, dbuf + 1107, lane, t);
        __syncwarp();
        dwt_level<32, 15>(bufA, bufB, dbuf + 1131, lane, t);
        __syncwarp();
        if (lane < 15) bufB[8 + lane] = softt(bufB[8 + lane], t);
        __syncwarp();
        idwt_level<32, 12>(bufB + 8, dbuf + 1131, bufA, lane);
        __syncwarp();
        idwt_level<32, 21>(bufA, dbuf + 1107, bufB, lane);
        __syncwarp();
        idwt_level<32, 38>(bufB, dbuf + 1066, bufA, lane);
    }
    __syncthreads();   // rejoin: a4-recon (len 76) in bufA at offset 0

    idwt_level<128, 73>(bufA, dbuf + 990, bufB, tid);
    __syncthreads();
    idwt_level<128, 142>(bufB, dbuf + 845, bufA, tid);
    __syncthreads();
    idwt_level<128, 281>(bufA, dbuf + 561, bufB, tid);
    __syncthreads();

    // ----- Final synthesis level (558 pairs): registers -> gmem directly -----
    {
        constexpr int P = 558;
        constexpr int CH = ((P + 127) >> 7) | 1;   // 5
        const int p0 = tid * CH;
        float2* out32 = (float2*)(recon + (size_t)row * NLEN);
        __half2* out16 = (__half2*)(g_Ah + (size_t)row * AROW);
        const float* abase = bufB;
        const float* dd = dbuf;
        if (p0 < P) {
            float a0 = abase[p0], a1 = abase[p0 + 1], a2 = abase[p0 + 2], a3 = abase[p0 + 3];
            float d0 = dd[p0],    d1 = dd[p0 + 1],    d2 = dd[p0 + 2],    d3 = dd[p0 + 3];
#pragma unroll
            for (int jj = 0; jj < CH; ++jj) {
                const int p = p0 + jj;
                float ye = a0 * c_LO[1];
                ye = fmaf(a1, c_LO[3], ye); ye = fmaf(a2, c_LO[5], ye); ye = fmaf(a3, c_LO[7], ye);
                ye = fmaf(d0, c_HI[1], ye); ye = fmaf(d1, c_HI[3], ye);
                ye = fmaf(d2, c_HI[5], ye); ye = fmaf(d3, c_HI[7], ye);
                float yo = a0 * c_LO[0];
                yo = fmaf(a1, c_LO[2], yo); yo = fmaf(a2, c_LO[4], yo); yo = fmaf(a3, c_LO[6], yo);
                yo = fmaf(d0, c_HI[0], yo); yo = fmaf(d1, c_HI[2], yo);
                yo = fmaf(d2, c_HI[4], yo); yo = fmaf(d3, c_HI[6], yo);
                if (p < P) {
                    out32[p] = make_float2(ye, yo);
                    out16[p] = __floats2half2_rn(ye, yo);
                }
                if (jj + 1 < CH) {
                    a0 = a1; a1 = a2; a2 = a3; a3 = abase[p0 + jj + 4];
                    d0 = d1; d1 = d2; d2 = d3; d3 = dd[p0 + jj + 4];
                }
            }
        }
        // zero-pad fp16 row tail k=1116..1119 (8 bytes)
        if (tid == 0)
            *(uint2*)(g_Ah + (size_t)row * AROW + NLEN) = make_uint2(0u, 0u);
    }
}

// ---------------------------------------------------------------------------
// W1 fp16 precompute: panels [35][112][32] (n padded to 112, k padded to
// 1120), k-panel-major so GEMM copies are contiguous uint4s.
// ---------------------------------------------------------------------------
#define KP2  35
#define NPAD 112
#define BTOT (KP2 * NPAD * 32)
__device__ __half g_Bh[BTOT];

__global__ __launch_bounds__(256) void w1_split_kernel(const float* __restrict__ W1)
{
    int i = blockIdx.x * 256 + threadIdx.x;
    if (i >= BTOT) return;
    int kk = i & 31;
    int n  = (i >> 5) % NPAD;
    int p  = i / (NPAD * 32);
    int k  = p * 32 + kk;
    float v = (n < HDIM && k < NLEN) ? W1[(size_t)n * NLEN + k] : 0.0f;
    g_Bh[i] = __float2half(v);
}

// ---------------------------------------------------------------------------
// Kernel 2: wmma fp16 GEMM (single term) + fused sigmoid/W2 reduction.
// A read as fp16 from g_Ah (half the DRAM traffic of fp32; no convert).
// Block: 128 rows x 112 cols, BK=32 (35 panels), 512 threads = 16 warps.
// ---------------------------------------------------------------------------
#define GBM 128
#define GTHREADS 512
#define ALD 40      // A smem ld (elements)
#define BLD 40      // B smem ld (elements, stride between n columns)
#define ELD 120     // epilogue smem ld (floats)
#define GEMM_SMEM (GBM * ELD * 4)   // epilogue view dominates

__global__ __launch_bounds__(GTHREADS) void mlp_wmma_kernel(
    const float* __restrict__ b1,
    const float* __restrict__ W2,
    const float* __restrict__ b2,
    float* __restrict__ reg)
{
    extern __shared__ __align__(16) char smem[];
    __shared__ float b1s[NPAD];
    __shared__ float w2s[NPAD];

    __half* Ah = (__half*)(smem);              // [128][40] 10240 B
    char* BhB  = smem + 10240;                 // [112][40]  8960 B
    float* eps = (float*)smem;                 // [128][120]

    const int tid = threadIdx.x;
    const int wid = tid >> 5;
    const int wm = wid >> 1;      // m-tile 0..7
    const int wn = wid & 1;       // n-half 0..1
    const int NT = wn ? 3 : 4;    // tiles in this half (cols 0..63 / 64..111)
    const int row0 = blockIdx.x * GBM;

    if (tid < NPAD) {
        b1s[tid] = (tid < HDIM) ? b1[tid] : 0.0f;
        w2s[tid] = (tid < HDIM) ? W2[tid] : 0.0f;
    }

    wmma::fragment<wmma::accumulator, 16, 16, 16, float> acc[4];
#pragma unroll
    for (int nt = 0; nt < 4; ++nt) wmma::fill_fragment(acc[nt], 0.0f);

    const int r = tid >> 2;       // 0..127 : A row this thread loads
    const int q = tid & 3;        // 0..3   : which 8-half chunk of the 32-k panel
    const int bj = tid;           // B copy index (tid < 448 active)
    const int ao = r * ALD + q * 8;

    // --- prefetch registers
    uint4 va, vbh0;
    const __half* arow = g_Ah + (size_t)(row0 + r) * AROW + q * 8;
    {
        va = *(const uint4*)(arow);                    // panel 0
        if (bj < 448) vbh0 = ((const uint4*)g_Bh)[bj];
    }

    for (int p = 0; p < KP2; ++p) {
        // ---- store A panel p (raw fp16 copy, no convert)
        *(uint4*)(Ah + ao) = va;
        // ---- store B panel p from registers
        if (bj < 448) {
            const int n = bj >> 2, kq = bj & 3;
            *(uint4*)(BhB + (n * BLD + kq * 8) * 2) = vbh0;
        }
        __syncthreads();

        // ---- prefetch next panel while MMAs run
        if (p + 1 < KP2) {
            va = *(const uint4*)(arow + (p + 1) * 32);
            if (bj < 448) vbh0 = ((const uint4*)g_Bh)[(p + 1) * 448 + bj];
        }

        // ---- MMAs: 2 k-steps of 16, single term
#pragma unroll
        for (int ks = 0; ks < 2; ++ks) {
            wmma::fragment<wmma::matrix_a, 16, 16, 16, __half, wmma::row_major> fa;
            wmma::load_matrix_sync(fa, Ah + wm * 16 * ALD + ks * 16, ALD);
#pragma unroll
            for (int nt = 0; nt < 4; ++nt) {
                if (nt < NT) {
                    const int n0 = (wn * 4 + nt) * 16;
                    wmma::fragment<wmma::matrix_b, 16, 16, 16, __half, wmma::col_major> fb;
                    wmma::load_matrix_sync(fb, (__half*)BhB + n0 * BLD + ks * 16, BLD);
                    wmma::mma_sync(acc[nt], fa, fb, acc[nt]);
                }
            }
        }
        __syncthreads();
    }

    // ---- epilogue: dump accumulators, sigmoid + W2 reduce
#pragma unroll
    for (int nt = 0; nt < 4; ++nt) {
        if (nt < NT) {
            wmma::store_matrix_sync(eps + wm * 16 * ELD + (wn * 4 + nt) * 16,
                                    acc[nt], ELD, wmma::mem_row_major);
        }
    }
    __syncthreads();

    {
        const float* er = eps + r * ELD;
        float s = 0.0f;
        const int c0 = q * 28;
#pragma unroll
        for (int c = 0; c < 28; ++c) {
            float pre = er[c0 + c] + b1s[c0 + c];
            float h = 1.0f / (1.0f + __expf(-pre));
            s = fmaf(h, w2s[c0 + c], s);   // w2s==0 beyond HDIM
        }
        s += __shfl_xor_sync(0xFFFFFFFFu, s, 1);
        s += __shfl_xor_sync(0xFFFFFFFFu, s, 2);
        if (q == 0) reg[row0 + r] = s + b2[0];
    }
}

// ---------------------------------------------------------------------------
extern "C" void kernel_launch(void* const* d_in, const int* in_sizes, int n_in,
                              void* d_out, int out_size)
{
    const float* x   = (const float*)d_in[0];
    const float* thr = (const float*)d_in[1];
    const float* W1  = (const float*)d_in[2];
    const float* b1  = (const float*)d_in[3];
    const float* W2  = (const float*)d_in[4];
    const float* b2  = (const float*)d_in[5];

    float* recon = (float*)d_out;
    float* reg   = (float*)d_out + (size_t)BATCH * NLEN;

    cudaFuncSetAttribute(mlp_wmma_kernel,
                         cudaFuncAttributeMaxDynamicSharedMemorySize, GEMM_SMEM);

    wavelet_kernel<<<BATCH, 128>>>(x, thr, recon);
    w1_split_kernel<<<(BTOT + 255) / 256, 256>>>(W1);
    mlp_wmma_kernel<<<BATCH / GBM, GTHREADS, GEMM_SMEM>>>(b1, W2, b2, reg);
}

// round 15
// speedup vs baseline: 1.2638x; 1.2638x over previous
#include <cuda_runtime.h>
#include <cuda_fp16.h>
#include <mma.h>
#include <cstdint>
#include <math.h>

using namespace nvcuda;

#define BATCH 32768
#define NLEN  1116
#define AROW  1120   // fp16 A row stride (padded)
#define HDIM  100

// ---------------------------------------------------------------------------
// fp16 copy of recon, written by wavelet, consumed by mlp GEMM (73.4 MB)
// ---------------------------------------------------------------------------
__device__ __half g_Ah[(size_t)BATCH * AROW];

// ---------------------------------------------------------------------------
// sym4 filters
// ---------------------------------------------------------------------------
__constant__ float c_LO[8] = {
    -0.010597401784997278f,  0.032883011666982945f,  0.030841381835986965f,
    -0.18703481171888114f,  -0.02798376941698385f,   0.6308807679295904f,
     0.7148465705525415f,    0.23037781330885523f};
__constant__ float c_HI[8] = {
    -0.23037781330885523f,   0.7148465705525415f,   -0.6308807679295904f,
    -0.02798376941698385f,   0.18703481171888114f,   0.030841381835986965f,
    -0.032883011666982945f, -0.010597401784997278f};

__device__ __forceinline__ float softt(float v, float t) {
    float av = fabsf(v);
    return (av > t) ? copysignf(av - t, v) : 0.0f;
}

// One DWT level, COMPILE-TIME size M, T threads. Fully unrolled inner loop.
template <int T, int M>
__device__ __forceinline__ void dwt_level(const float* cur, float* nxt, float* dd,
                                          int id, float t)
{
    constexpr int CH = ((M + T - 1) / T) | 1;   // odd -> <=2-way LDS conflicts
    const int j0 = id * CH;
    if (j0 < M) {
        const float* p = cur + 2 + 2 * j0;
        float w0 = p[0], w1 = p[1], w2 = p[2], w3 = p[3];
        float w4 = p[4], w5 = p[5], w6 = p[6], w7 = p[7];
#pragma unroll
        for (int jj = 0; jj < CH; ++jj) {
            const int j = j0 + jj;
            float lo = w0 * c_LO[7];
            lo = fmaf(w1, c_LO[6], lo); lo = fmaf(w2, c_LO[5], lo);
            lo = fmaf(w3, c_LO[4], lo); lo = fmaf(w4, c_LO[3], lo);
            lo = fmaf(w5, c_LO[2], lo); lo = fmaf(w6, c_LO[1], lo);
            lo = fmaf(w7, c_LO[0], lo);
            float hi = w0 * c_HI[7];
            hi = fmaf(w1, c_HI[6], hi); hi = fmaf(w2, c_HI[5], hi);
            hi = fmaf(w3, c_HI[4], hi); hi = fmaf(w4, c_HI[3], hi);
            hi = fmaf(w5, c_HI[2], hi); hi = fmaf(w6, c_HI[1], hi);
            hi = fmaf(w7, c_HI[0], hi);
            if (j < M) {
                nxt[8 + j] = lo;
                dd[j] = softt(hi, t);
            }
            if (jj + 1 < CH) {
                w0 = w2; w1 = w3; w2 = w4; w3 = w5; w4 = w6; w5 = w7;
                float2 nx = *(const float2*)(p + 8 + 2 * jj);   // immediate offset
                w6 = nx.x; w7 = nx.y;                            // lookahead slack ok
            }
        }
    }
    if (id < 6) nxt[2 + id] = 0.0f;
    if (id < 8) nxt[8 + M + id] = 0.0f;
}

// One IDWT level, COMPILE-TIME pair count P (smem -> smem).
template <int T, int P>
__device__ __forceinline__ void idwt_level(const float* abase, const float* dd,
                                           float* obase, int id)
{
    constexpr int CH = ((P + T - 1) / T) | 1;
    const int p0 = id * CH;
    if (p0 < P) {
        float a0 = abase[p0], a1 = abase[p0 + 1], a2 = abase[p0 + 2], a3 = abase[p0 + 3];
        float d0 = dd[p0],    d1 = dd[p0 + 1],    d2 = dd[p0 + 2],    d3 = dd[p0 + 3];
#pragma unroll
        for (int jj = 0; jj < CH; ++jj) {
            const int p = p0 + jj;
            float ye = a0 * c_LO[1];
            ye = fmaf(a1, c_LO[3], ye); ye = fmaf(a2, c_LO[5], ye); ye = fmaf(a3, c_LO[7], ye);
            ye = fmaf(d0, c_HI[1], ye); ye = fmaf(d1, c_HI[3], ye);
            ye = fmaf(d2, c_HI[5], ye); ye = fmaf(d3, c_HI[7], ye);
            float yo = a0 * c_LO[0];
            yo = fmaf(a1, c_LO[2], yo); yo = fmaf(a2, c_LO[4], yo); yo = fmaf(a3, c_LO[6], yo);
            yo = fmaf(d0, c_HI[0], yo); yo = fmaf(d1, c_HI[2], yo);
            yo = fmaf(d2, c_HI[4], yo); yo = fmaf(d3, c_HI[6], yo);
            if (p < P) ((float2*)obase)[p] = make_float2(ye, yo);
            if (jj + 1 < CH) {
                a0 = a1; a1 = a2; a2 = a3; a3 = abase[p0 + jj + 4];   // lookahead ok
                d0 = d1; d1 = d2; d2 = d3; d3 = dd[p0 + jj + 4];
            }
        }
    }
}

// ---------------------------------------------------------------------------
// Kernel 1: per-row 7-level DWT -> soft threshold -> IDWT. (R13 structure)
// Copy-out emits BOTH fp32 recon (float4, coalesced) and fp16 g_Ah row
// (uint4 of 8 halves, coalesced).
// ---------------------------------------------------------------------------
__global__ __launch_bounds__(128) void wavelet_kernel(
    const float* __restrict__ x,
    const float* __restrict__ thr,
    float* __restrict__ recon)
{
    __shared__ __align__(16) float bufA[1140];
    __shared__ __align__(16) float bufB[1140];
    __shared__ __align__(16) float dbuf[1152];

    const int tid = threadIdx.x;
    const int row = blockIdx.x;
    const float t = fmaxf(thr[0], 0.01f);

    {
        const float4* xr = (const float4*)(x + (size_t)row * NLEN);
        float4* dst = (float4*)(bufA + 8);
        for (int i = tid; i < 279; i += 128) dst[i] = xr[i];
        if (tid < 6) bufA[2 + tid] = 0.0f;
        if (tid < 8) bufA[8 + NLEN + tid] = 0.0f;
    }
    __syncthreads();

    dwt_level<128, 561>(bufA, bufB, dbuf + 0,   tid, t);
    __syncthreads();
    dwt_level<128, 284>(bufB, bufA, dbuf + 561, tid, t);
    __syncthreads();
    dwt_level<128, 145>(bufA, bufB, dbuf + 845, tid, t);
    __syncthreads();

    if (tid < 32) {
        const int lane = tid;
        dwt_level<32, 76>(bufB, bufA, dbuf + 990,  lane, t);
        __syncwarp();
        dwt_level<32, 41>(bufA, bufB, dbuf + 1066, lane, t);
        __syncwarp();
        dwt_level<32, 24>(bufB, bufA, dbuf + 1107, lane, t);
        __syncwarp();
        dwt_level<32, 15>(bufA, bufB, dbuf + 1131, lane, t);
        __syncwarp();
        if (lane < 15) bufB[8 + lane] = softt(bufB[8 + lane], t);
        __syncwarp();
        idwt_level<32, 12>(bufB + 8, dbuf + 1131, bufA, lane);
        __syncwarp();
        idwt_level<32, 21>(bufA, dbuf + 1107, bufB, lane);
        __syncwarp();
        idwt_level<32, 38>(bufB, dbuf + 1066, bufA, lane);
    }
    __syncthreads();   // rejoin: a4-recon (len 76) in bufA at offset 0

    idwt_level<128, 73>(bufA, dbuf + 990, bufB, tid);
    __syncthreads();
    idwt_level<128, 142>(bufB, dbuf + 845, bufA, tid);
    __syncthreads();
    idwt_level<128, 281>(bufA, dbuf + 561, bufB, tid);
    __syncthreads();
    idwt_level<128, 558>(bufB, dbuf + 0, bufA, tid);
    __syncthreads();

    // ----- Coalesced copy-out: fp32 recon + fp16 g_Ah -----
    {
        float4* out32 = (float4*)(recon + (size_t)row * NLEN);
        uint4* out16 = (uint4*)(g_Ah + (size_t)row * AROW);   // 8 halves per uint4
        const float4* a4 = (const float4*)bufA;
        // fp32: 279 float4
        for (int i = tid; i < 279; i += 128) out32[i] = a4[i];
        // fp16: 140 uint4 (8 floats -> 8 halves each); last one pads k=1116..1119
        for (int i = tid; i < 140; i += 128) {
            float4 v0 = a4[2 * i];
            float4 v1 = (2 * i + 1 < 279) ? a4[2 * i + 1]
                                          : make_float4(0.f, 0.f, 0.f, 0.f);
            if (i == 139) {   // elements 1112..1119: 1112..1115 real, rest 0
                v1 = make_float4(0.f, 0.f, 0.f, 0.f);
            }
            __half2 h0 = __floats2half2_rn(v0.x, v0.y);
            __half2 h1 = __floats2half2_rn(v0.z, v0.w);
            __half2 h2 = __floats2half2_rn(v1.x, v1.y);
            __half2 h3 = __floats2half2_rn(v1.z, v1.w);
            out16[i] = make_uint4(*(uint32_t*)&h0, *(uint32_t*)&h1,
                                  *(uint32_t*)&h2, *(uint32_t*)&h3);
        }
    }
}

// ---------------------------------------------------------------------------
// W1 fp16 precompute: panels [35][112][32] (n padded to 112, k padded to
// 1120), k-panel-major so GEMM copies are contiguous uint4s.
// ---------------------------------------------------------------------------
#define KP2  35
#define NPAD 112
#define BTOT (KP2 * NPAD * 32)
__device__ __half g_Bh[BTOT];

__global__ __launch_bounds__(256) void w1_split_kernel(const float* __restrict__ W1)
{
    int i = blockIdx.x * 256 + threadIdx.x;
    if (i >= BTOT) return;
    int kk = i & 31;
    int n  = (i >> 5) % NPAD;
    int p  = i / (NPAD * 32);
    int k  = p * 32 + kk;
    float v = (n < HDIM && k < NLEN) ? W1[(size_t)n * NLEN + k] : 0.0f;
    g_Bh[i] = __float2half(v);
}

// ---------------------------------------------------------------------------
// Kernel 2: wmma fp16 GEMM (single term) + fused sigmoid/W2 reduction.
// A read as fp16 from g_Ah. (unchanged R14 — measured ~46us)
// ---------------------------------------------------------------------------
#define GBM 128
#define GTHREADS 512
#define ALD 40
#define BLD 40
#define ELD 120
#define GEMM_SMEM (GBM * ELD * 4)

__global__ __launch_bounds__(GTHREADS) void mlp_wmma_kernel(
    const float* __restrict__ b1,
    const float* __restrict__ W2,
    const float* __restrict__ b2,
    float* __restrict__ reg)
{
    extern __shared__ __align__(16) char smem[];
    __shared__ float b1s[NPAD];
    __shared__ float w2s[NPAD];

    __half* Ah = (__half*)(smem);              // [128][40] 10240 B
    char* BhB  = smem + 10240;                 // [112][40]  8960 B
    float* eps = (float*)smem;                 // [128][120]

    const int tid = threadIdx.x;
    const int wid = tid >> 5;
    const int wm = wid >> 1;
    const int wn = wid & 1;
    const int NT = wn ? 3 : 4;
    const int row0 = blockIdx.x * GBM;

    if (tid < NPAD) {
        b1s[tid] = (tid < HDIM) ? b1[tid] : 0.0f;
        w2s[tid] = (tid < HDIM) ? W2[tid] : 0.0f;
    }

    wmma::fragment<wmma::accumulator, 16, 16, 16, float> acc[4];
#pragma unroll
    for (int nt = 0; nt < 4; ++nt) wmma::fill_fragment(acc[nt], 0.0f);

    const int r = tid >> 2;
    const int q = tid & 3;
    const int bj = tid;
    const int ao = r * ALD + q * 8;

    uint4 va, vbh0;
    const __half* arow = g_Ah + (size_t)(row0 + r) * AROW + q * 8;
    {
        va = *(const uint4*)(arow);
        if (bj < 448) vbh0 = ((const uint4*)g_Bh)[bj];
    }

    for (int p = 0; p < KP2; ++p) {
        *(uint4*)(Ah + ao) = va;
        if (bj < 448) {
            const int n = bj >> 2, kq = bj & 3;
            *(uint4*)(BhB + (n * BLD + kq * 8) * 2) = vbh0;
        }
        __syncthreads();

        if (p + 1 < KP2) {
            va = *(const uint4*)(arow + (p + 1) * 32);
            if (bj < 448) vbh0 = ((const uint4*)g_Bh)[(p + 1) * 448 + bj];
        }

#pragma unroll
        for (int ks = 0; ks < 2; ++ks) {
            wmma::fragment<wmma::matrix_a, 16, 16, 16, __half, wmma::row_major> fa;
            wmma::load_matrix_sync(fa, Ah + wm * 16 * ALD + ks * 16, ALD);
#pragma unroll
            for (int nt = 0; nt < 4; ++nt) {
                if (nt < NT) {
                    const int n0 = (wn * 4 + nt) * 16;
                    wmma::fragment<wmma::matrix_b, 16, 16, 16, __half, wmma::col_major> fb;
                    wmma::load_matrix_sync(fb, (__half*)BhB + n0 * BLD + ks * 16, BLD);
                    wmma::mma_sync(acc[nt], fa, fb, acc[nt]);
                }
            }
        }
        __syncthreads();
    }

#pragma unroll
    for (int nt = 0; nt < 4; ++nt) {
        if (nt < NT) {
            wmma::store_matrix_sync(eps + wm * 16 * ELD + (wn * 4 + nt) * 16,
                                    acc[nt], ELD, wmma::mem_row_major);
        }
    }
    __syncthreads();

    {
        const float* er = eps + r * ELD;
        float s = 0.0f;
        const int c0 = q * 28;
#pragma unroll
        for (int c = 0; c < 28; ++c) {
            float pre = er[c0 + c] + b1s[c0 + c];
            float h = 1.0f / (1.0f + __expf(-pre));
            s = fmaf(h, w2s[c0 + c], s);
        }
        s += __shfl_xor_sync(0xFFFFFFFFu, s, 1);
        s += __shfl_xor_sync(0xFFFFFFFFu, s, 2);
        if (q == 0) reg[row0 + r] = s + b2[0];
    }
}

// ---------------------------------------------------------------------------
extern "C" void kernel_launch(void* const* d_in, const int* in_sizes, int n_in,
                              void* d_out, int out_size)
{
    const float* x   = (const float*)d_in[0];
    const float* thr = (const float*)d_in[1];
    const float* W1  = (const float*)d_in[2];
    const float* b1  = (const float*)d_in[3];
    const float* W2  = (const float*)d_in[4];
    const float* b2  = (const float*)d_in[5];

    float* recon = (float*)d_out;
    float* reg   = (float*)d_out + (size_t)BATCH * NLEN;

    cudaFuncSetAttribute(mlp_wmma_kernel,
                         cudaFuncAttributeMaxDynamicSharedMemorySize, GEMM_SMEM);

    wavelet_kernel<<<BATCH, 128>>>(x, thr, recon);
    w1_split_kernel<<<(BTOT + 255) / 256, 256>>>(W1);
    mlp_wmma_kernel<<<BATCH / GBM, GTHREADS, GEMM_SMEM>>>(b1, W2, b2, reg);
}